// round 1
// baseline (speedup 1.0000x reference)
#include <cuda_runtime.h>
#include <mma.h>
#include <cstdint>

using namespace nvcuda;

#define BS   4
#define TN   512
#define DM   512
#define HN   8
#define HDN  64
#define LN_  6
#define VN   50257
#define EPSV 1e-5f

// ---------------- scratch (static device arrays; no allocation) ----------------
__device__ float g_h   [BS*TN*DM];        // residual stream [2048,512]
__device__ float g_tmp [BS*TN*DM];        // LN output
__device__ float g_qkv [BS*TN*3*DM];      // [2048,1536]
__device__ float g_sc  [BS*HN*TN*TN];     // attention scores [32,512,512]
__device__ float g_ff  [BS*TN*4*DM];      // [2048,2048]
__device__ float g_att [BS*TN*DM];        // attention output

// ---------------- embedding ----------------
__global__ void embed_k(const int* __restrict__ x, const float* __restrict__ tok,
                        const float* __restrict__ pos, float* __restrict__ h) {
    int i = blockIdx.x * 256 + threadIdx.x;
    if (i >= BS*TN*DM) return;
    int d  = i % DM;
    int bt = i / DM;
    int t  = bt % TN;
    h[i] = tok[(size_t)x[bt] * DM + d] + pos[t * DM + d];
}

// ---------------- layernorm (one row per block, 256 threads) ----------------
__global__ __launch_bounds__(256) void ln_k(const float* __restrict__ in, float* __restrict__ out,
                                            const float* __restrict__ sc, const float* __restrict__ bi) {
    __shared__ float s1[256], s2[256];
    int row = blockIdx.x;
    int tid = threadIdx.x;
    const float* xr = in + (size_t)row * DM;
    float a = xr[tid], b = xr[tid + 256];
    s1[tid] = a + b;
    s2[tid] = a * a + b * b;
    __syncthreads();
    for (int s = 128; s > 0; s >>= 1) {
        if (tid < s) { s1[tid] += s1[tid + s]; s2[tid] += s2[tid + s]; }
        __syncthreads();
    }
    float mean = s1[0] * (1.0f / DM);
    float var  = s2[0] * (1.0f / DM) - mean * mean;
    float r    = rsqrtf(var + EPSV);
    out[(size_t)row * DM + tid]       = (a - mean) * r * sc[tid]       + bi[tid];
    out[(size_t)row * DM + tid + 256] = (b - mean) * r * sc[tid + 256] + bi[tid + 256];
}

// ---------------- TF32 wmma GEMM: C = A[MxK] @ B[KxN] + bias (+gelu / +residual) --------
// MODE 0: bias only; MODE 1: bias + exact gelu; MODE 2: bias + residual add
template <int MODE>
__global__ __launch_bounds__(128) void gemm_k(const float* __restrict__ A, const float* __restrict__ B,
                                              const float* __restrict__ bias, const float* __restrict__ res,
                                              float* __restrict__ C, int M, int N, int K) {
    __shared__ union SM {
        struct { float As[64][40]; float Bs[32][72]; } L;
        float Cs[64][72];
    } sm;

    int tid  = threadIdx.x;
    int warp = tid >> 5;
    int wm   = warp >> 1;   // 0..1
    int wn   = warp & 1;    // 0..1
    int m0   = blockIdx.y * 64;
    int n0   = blockIdx.x * 64;

    wmma::fragment<wmma::accumulator, 16, 16, 8, float> acc[2][2];
    #pragma unroll
    for (int i = 0; i < 2; i++)
        #pragma unroll
        for (int j = 0; j < 2; j++)
            wmma::fill_fragment(acc[i][j], 0.0f);

    for (int k0 = 0; k0 < K; k0 += 32) {
        // load A tile 64x32 (K % 4 == 0 for all our shapes -> float4 ok)
        #pragma unroll
        for (int r = 0; r < 4; r++) {
            int row = r * 16 + (tid >> 3);
            int kk  = (tid & 7) * 4;
            float4 v = *(const float4*)&A[(size_t)(m0 + row) * K + k0 + kk];
            sm.L.As[row][kk + 0] = v.x;
            sm.L.As[row][kk + 1] = v.y;
            sm.L.As[row][kk + 2] = v.z;
            sm.L.As[row][kk + 3] = v.w;
        }
        // load B tile 32x64 (scalar, guard N)
        #pragma unroll
        for (int r = 0; r < 16; r++) {
            int idx = r * 128 + tid;
            int rr  = idx >> 6;
            int cc  = idx & 63;
            int col = n0 + cc;
            sm.L.Bs[rr][cc] = (col < N) ? B[(size_t)(k0 + rr) * N + col] : 0.0f;
        }
        __syncthreads();
        #pragma unroll
        for (int kk = 0; kk < 32; kk += 8) {
            wmma::fragment<wmma::matrix_a, 16, 16, 8, wmma::precision::tf32, wmma::row_major> af[2];
            wmma::fragment<wmma::matrix_b, 16, 16, 8, wmma::precision::tf32, wmma::row_major> bf[2];
            #pragma unroll
            for (int i = 0; i < 2; i++) {
                wmma::load_matrix_sync(af[i], &sm.L.As[wm * 32 + i * 16][kk], 40);
                #pragma unroll
                for (int t = 0; t < af[i].num_elements; t++) af[i].x[t] = wmma::__float_to_tf32(af[i].x[t]);
            }
            #pragma unroll
            for (int j = 0; j < 2; j++) {
                wmma::load_matrix_sync(bf[j], &sm.L.Bs[kk][wn * 32 + j * 16], 72);
                #pragma unroll
                for (int t = 0; t < bf[j].num_elements; t++) bf[j].x[t] = wmma::__float_to_tf32(bf[j].x[t]);
            }
            #pragma unroll
            for (int i = 0; i < 2; i++)
                #pragma unroll
                for (int j = 0; j < 2; j++)
                    wmma::mma_sync(acc[i][j], af[i], bf[j], acc[i][j]);
        }
        __syncthreads();
    }

    // stage accumulators to shared, then fused epilogue
    #pragma unroll
    for (int i = 0; i < 2; i++)
        #pragma unroll
        for (int j = 0; j < 2; j++)
            wmma::store_matrix_sync(&sm.Cs[wm * 32 + i * 16][wn * 32 + j * 16], acc[i][j], 72,
                                    wmma::mem_row_major);
    __syncthreads();

    #pragma unroll
    for (int r = 0; r < 32; r++) {
        int idx = r * 128 + tid;
        int rr  = idx >> 6;
        int cc  = idx & 63;
        int col = n0 + cc;
        if (col >= N) continue;
        size_t gi = (size_t)(m0 + rr) * N + col;
        float v = sm.Cs[rr][cc] + bias[col];
        if (MODE == 1) v = 0.5f * v * (1.0f + erff(v * 0.70710678118654752f));
        if (MODE == 2) v += res[gi];
        C[gi] = v;
    }
}

// ---------------- attention: S = Q K^T * scale with causal mask ----------------
__global__ __launch_bounds__(256) void scores_k(const float* __restrict__ qkv, float* __restrict__ sc) {
    int bh = blockIdx.z;
    int b  = bh >> 3;
    int h  = bh & 7;
    int q0 = blockIdx.y << 6;
    int j0 = blockIdx.x << 6;
    float* out = sc + (size_t)bh * TN * TN;
    int tid = threadIdx.x;

    if (j0 > q0) {  // fully masked tile
        #pragma unroll
        for (int r = 0; r < 16; r++) {
            int idx = r * 256 + tid;
            out[(size_t)(q0 + (idx >> 6)) * TN + j0 + (idx & 63)] = -1e30f;
        }
        return;
    }

    __shared__ float Qs[64][65], Ks[64][65];
    #pragma unroll
    for (int r = 0; r < 16; r++) {
        int idx = r * 256 + tid;
        int rr = idx >> 6, cc = idx & 63;
        Qs[rr][cc] = qkv[((size_t)(b * TN + q0 + rr)) * 1536 + h * 64 + cc];
        Ks[rr][cc] = qkv[((size_t)(b * TN + j0 + rr)) * 1536 + 512 + h * 64 + cc];
    }
    __syncthreads();

    int tx = tid & 15, ty = tid >> 4;
    float acc[4][4] = {};
    #pragma unroll 8
    for (int d = 0; d < 64; d++) {
        float a0 = Qs[ty * 4 + 0][d], a1 = Qs[ty * 4 + 1][d], a2 = Qs[ty * 4 + 2][d], a3 = Qs[ty * 4 + 3][d];
        float b0 = Ks[tx * 4 + 0][d], b1 = Ks[tx * 4 + 1][d], b2 = Ks[tx * 4 + 2][d], b3 = Ks[tx * 4 + 3][d];
        acc[0][0] += a0 * b0; acc[0][1] += a0 * b1; acc[0][2] += a0 * b2; acc[0][3] += a0 * b3;
        acc[1][0] += a1 * b0; acc[1][1] += a1 * b1; acc[1][2] += a1 * b2; acc[1][3] += a1 * b3;
        acc[2][0] += a2 * b0; acc[2][1] += a2 * b1; acc[2][2] += a2 * b2; acc[2][3] += a2 * b3;
        acc[3][0] += a3 * b0; acc[3][1] += a3 * b1; acc[3][2] += a3 * b2; acc[3][3] += a3 * b3;
    }
    #pragma unroll
    for (int i = 0; i < 4; i++)
        #pragma unroll
        for (int j = 0; j < 4; j++) {
            int row = q0 + ty * 4 + i;
            int col = j0 + tx * 4 + j;
            out[(size_t)row * TN + col] = (col <= row) ? acc[i][j] * 0.125f : -1e30f;
        }
}

// ---------------- softmax over rows of scores (warp per row) ----------------
__global__ __launch_bounds__(256) void softmax_k(float* __restrict__ sc) {
    int warp = threadIdx.x >> 5, lane = threadIdx.x & 31;
    size_t row = (size_t)blockIdx.x * 8 + warp;
    float* p = sc + row * TN;
    float v[16];
    float mx = -3.4e38f;
    #pragma unroll
    for (int i = 0; i < 16; i++) { v[i] = p[lane + 32 * i]; mx = fmaxf(mx, v[i]); }
    #pragma unroll
    for (int o = 16; o; o >>= 1) mx = fmaxf(mx, __shfl_xor_sync(0xffffffffu, mx, o));
    float s = 0.0f;
    #pragma unroll
    for (int i = 0; i < 16; i++) { v[i] = expf(v[i] - mx); s += v[i]; }
    #pragma unroll
    for (int o = 16; o; o >>= 1) s += __shfl_xor_sync(0xffffffffu, s, o);
    float inv = 1.0f / s;
    #pragma unroll
    for (int i = 0; i < 16; i++) p[lane + 32 * i] = v[i] * inv;
}

// ---------------- O = P @ V (causal: P cols > q0+63 are exactly 0) ----------------
__global__ __launch_bounds__(256) void av_k(const float* __restrict__ sc, const float* __restrict__ qkv,
                                            float* __restrict__ o) {
    int bh = blockIdx.z;
    int b  = bh >> 3;
    int h  = bh & 7;
    int q0 = blockIdx.y << 6;
    const float* P = sc + (size_t)bh * TN * TN;

    __shared__ float Ps[64][65], Vs[64][65];
    int tid = threadIdx.x;
    int tx = tid & 15, ty = tid >> 4;
    float acc[4][4] = {};

    for (int k0 = 0; k0 <= q0; k0 += 64) {
        #pragma unroll
        for (int r = 0; r < 16; r++) {
            int idx = r * 256 + tid;
            int rr = idx >> 6, cc = idx & 63;
            Ps[rr][cc] = P[(size_t)(q0 + rr) * TN + k0 + cc];
            Vs[rr][cc] = qkv[((size_t)(b * TN + k0 + rr)) * 1536 + 1024 + h * 64 + cc];
        }
        __syncthreads();
        #pragma unroll 8
        for (int kk = 0; kk < 64; kk++) {
            float a0 = Ps[ty * 4 + 0][kk], a1 = Ps[ty * 4 + 1][kk], a2 = Ps[ty * 4 + 2][kk], a3 = Ps[ty * 4 + 3][kk];
            float b0 = Vs[kk][tx * 4 + 0], b1 = Vs[kk][tx * 4 + 1], b2 = Vs[kk][tx * 4 + 2], b3 = Vs[kk][tx * 4 + 3];
            acc[0][0] += a0 * b0; acc[0][1] += a0 * b1; acc[0][2] += a0 * b2; acc[0][3] += a0 * b3;
            acc[1][0] += a1 * b0; acc[1][1] += a1 * b1; acc[1][2] += a1 * b2; acc[1][3] += a1 * b3;
            acc[2][0] += a2 * b0; acc[2][1] += a2 * b1; acc[2][2] += a2 * b2; acc[2][3] += a2 * b3;
            acc[3][0] += a3 * b0; acc[3][1] += a3 * b1; acc[3][2] += a3 * b2; acc[3][3] += a3 * b3;
        }
        __syncthreads();
    }
    #pragma unroll
    for (int i = 0; i < 4; i++)
        #pragma unroll
        for (int j = 0; j < 4; j++)
            o[((size_t)(b * TN + q0 + ty * 4 + i)) * DM + h * 64 + tx * 4 + j] = acc[i][j];
}

// ---------------- launch ----------------
extern "C" void kernel_launch(void* const* d_in, const int* in_sizes, int n_in,
                              void* d_out, int out_size) {
    const int*   x      = (const int*)  d_in[0];
    const float* tok    = (const float*)d_in[1];
    const float* pos    = (const float*)d_in[2];
    const float* qkv_w  = (const float*)d_in[3];
    const float* qkv_b  = (const float*)d_in[4];
    const float* out_w  = (const float*)d_in[5];
    const float* out_b  = (const float*)d_in[6];
    const float* ln1_s  = (const float*)d_in[7];
    const float* ln1_b  = (const float*)d_in[8];
    const float* ff1_w  = (const float*)d_in[9];
    const float* ff1_b  = (const float*)d_in[10];
    const float* ff2_w  = (const float*)d_in[11];
    const float* ff2_b  = (const float*)d_in[12];
    const float* ln2_s  = (const float*)d_in[13];
    const float* ln2_b  = (const float*)d_in[14];
    const float* lnf_s  = (const float*)d_in[15];
    const float* lnf_b  = (const float*)d_in[16];
    const float* head_w = (const float*)d_in[17];
    const float* head_b = (const float*)d_in[18];
    float* out = (float*)d_out;

    float *h, *tmp, *qkv, *sc, *ff, *att;
    cudaGetSymbolAddress((void**)&h,   g_h);
    cudaGetSymbolAddress((void**)&tmp, g_tmp);
    cudaGetSymbolAddress((void**)&qkv, g_qkv);
    cudaGetSymbolAddress((void**)&sc,  g_sc);
    cudaGetSymbolAddress((void**)&ff,  g_ff);
    cudaGetSymbolAddress((void**)&att, g_att);

    const int M = BS * TN;  // 2048

    embed_k<<<(BS*TN*DM + 255) / 256, 256>>>(x, tok, pos, h);

    for (int l = 0; l < LN_; l++) {
        const float* w_qkv = qkv_w + (size_t)l * DM * 3 * DM;
        const float* b_qkv = qkv_b + (size_t)l * 3 * DM;
        const float* w_out = out_w + (size_t)l * DM * DM;
        const float* b_out = out_b + (size_t)l * DM;
        const float* w_f1  = ff1_w + (size_t)l * DM * 4 * DM;
        const float* b_f1  = ff1_b + (size_t)l * 4 * DM;
        const float* w_f2  = ff2_w + (size_t)l * 4 * DM * DM;
        const float* b_f2  = ff2_b + (size_t)l * DM;

        // attention block
        ln_k<<<M, 256>>>(h, tmp, ln1_s + l * DM, ln1_b + l * DM);
        gemm_k<0><<<dim3(24, 32), 128>>>(tmp, w_qkv, b_qkv, nullptr, qkv, M, 3 * DM, DM);
        scores_k<<<dim3(8, 8, 32), 256>>>(qkv, sc);
        softmax_k<<<(BS * HN * TN) / 8, 256>>>(sc);
        av_k<<<dim3(1, 8, 32), 256>>>(sc, qkv, att);
        gemm_k<2><<<dim3(8, 32), 128>>>(att, w_out, b_out, h, h, M, DM, DM);

        // feed-forward block
        ln_k<<<M, 256>>>(h, tmp, ln2_s + l * DM, ln2_b + l * DM);
        gemm_k<1><<<dim3(32, 32), 128>>>(tmp, w_f1, b_f1, nullptr, ff, M, 4 * DM, DM);
        gemm_k<2><<<dim3(8, 32), 128>>>(ff, w_f2, b_f2, h, h, M, DM, 4 * DM);
    }

    // final LN + LM head
    ln_k<<<M, 256>>>(h, tmp, lnf_s, lnf_b);
    gemm_k<0><<<dim3((VN + 63) / 64, 32), 128>>>(tmp, head_w, head_b, nullptr, out, M, VN, DM);
}